// round 1
// baseline (speedup 1.0000x reference)
#include <cuda_runtime.h>

#define B_SZ  2
#define N_TOK 512
#define D     64
#define H     128
#define OUTD  64
#define TI    16
#define TJ    8

// Scratch (device globals — no runtime allocation allowed)
__device__ float g_xa[B_SZ * N_TOK * H];   // x @ W1[:D]  + b1  (pair_a / j contribution)
__device__ float g_xb[B_SZ * N_TOK * H];   // x @ W1[D:]        (pair_b / i contribution)
__device__ float g_pooled[B_SZ * H];       // sum over all pairs of h2

// ---------------------------------------------------------------------------
// Kernel A: xa/xb projection (+ zero g_pooled). 128 blocks x 128 threads.
// Each block handles 8 token rows to amortize the W1 read.
// ---------------------------------------------------------------------------
__global__ __launch_bounds__(128) void prep_kernel(const float* __restrict__ x,
                                                   const float* __restrict__ W1,
                                                   const float* __restrict__ b1)
{
    __shared__ float sx[8][D];
    const int t = threadIdx.x;
    const int row0 = blockIdx.x * 8;              // global row in [0, B*N)

    for (int e = t; e < 8 * D; e += 128)
        sx[e >> 6][e & 63] = x[row0 * D + e];
    __syncthreads();

    const int h = t;
    float accA[8], accB[8];
#pragma unroll
    for (int r = 0; r < 8; ++r) { accA[r] = 0.f; accB[r] = 0.f; }

    for (int d = 0; d < D; ++d) {
        const float wa = W1[d * H + h];
        const float wb = W1[(D + d) * H + h];
#pragma unroll
        for (int r = 0; r < 8; ++r) {
            const float xv = sx[r][d];
            accA[r] = fmaf(xv, wa, accA[r]);
            accB[r] = fmaf(xv, wb, accB[r]);
        }
    }
    const float bb = b1[h];
#pragma unroll
    for (int r = 0; r < 8; ++r) {
        g_xa[(row0 + r) * H + h] = accA[r] + bb;   // b1 folded in once per pair
        g_xb[(row0 + r) * H + h] = accB[r];
    }
    if (blockIdx.x == 0) { g_pooled[t] = 0.f; g_pooled[t + 128] = 0.f; }
}

// ---------------------------------------------------------------------------
// Kernel B (dominant): per CTA, 128 pairs (TIxTJ). Implicit GEMM
//   C[p,h] = relu(xa[j]+xb[i]) @ W2, epilogue relu(+b2) + column-sum over p.
// smem: sW2[128][128] | sA[128][128] (K-major) | sxa[8][132] | sxb[16][132]
// ---------------------------------------------------------------------------
__global__ __launch_bounds__(256) void pair_kernel(const float* __restrict__ W2,
                                                   const float* __restrict__ b2)
{
    extern __shared__ float smem[];
    float* sW2 = smem;                  // 16384 floats
    float* sA  = smem + 16384;          // 16384 floats, layout sA[k*128 + p]
    float* sxa = smem + 32768;          // 8  * 132 (padded: avoid bank conflicts)
    float* sxb = sxa + 8 * 132;         // 16 * 132

    const int b  = blockIdx.z;
    const int j0 = blockIdx.x * TJ;
    const int i0 = blockIdx.y * TI;
    const int t  = threadIdx.x;

    // Stage W2 (resident for whole block)
    const float4* W2v  = (const float4*)W2;
    float4*       sW2v = (float4*)sW2;
    for (int e = t; e < H * H / 4; e += 256) sW2v[e] = W2v[e];

    // Stage xa/xb row tiles (coalesced)
    const float* xa_base = g_xa + (b * N_TOK + j0) * H;
    const float* xb_base = g_xb + (b * N_TOK + i0) * H;
    for (int e = t; e < TJ * H; e += 256) { int r = e >> 7, k = e & 127; sxa[r * 132 + k] = xa_base[r * H + k]; }
    for (int e = t; e < TI * H; e += 256) { int r = e >> 7, k = e & 127; sxb[r * 132 + k] = xb_base[r * H + k]; }
    __syncthreads();

    // Phase 1: build A tile, K-major: sA[k][p] = relu(xa[j(p),k] + xb[i(p),k])
    for (int e = t; e < 128 * 128; e += 256) {
        const int k = e >> 7, p = e & 127;
        const float v = sxa[(p & 7) * 132 + k] + sxb[(p >> 3) * 132 + k];
        sA[e] = v > 0.f ? v : 0.f;
    }
    __syncthreads();

    // Phase 2: 8x8 register-blocked fp32 GEMM, 16x16 thread grid
    const int tx = t & 15, ty = t >> 4;
    const int pb4 = ty * 2;             // float4 index of pair base
    const int hb4 = tx * 2;             // float4 index of h base

    float acc[8][8];
#pragma unroll
    for (int a = 0; a < 8; ++a)
#pragma unroll
        for (int c = 0; c < 8; ++c) acc[a][c] = 0.f;

    const float4* sAv = (const float4*)sA;
#pragma unroll 2
    for (int k = 0; k < 128; ++k) {
        const float4 a0 = sAv[k * 32 + pb4];
        const float4 a1 = sAv[k * 32 + pb4 + 1];
        const float4 w0 = sW2v[k * 32 + hb4];
        const float4 w1 = sW2v[k * 32 + hb4 + 1];
        const float av[8] = {a0.x, a0.y, a0.z, a0.w, a1.x, a1.y, a1.z, a1.w};
        const float wv[8] = {w0.x, w0.y, w0.z, w0.w, w1.x, w1.y, w1.z, w1.w};
#pragma unroll
        for (int pi = 0; pi < 8; ++pi)
#pragma unroll
            for (int hi = 0; hi < 8; ++hi)
                acc[pi][hi] = fmaf(av[pi], wv[hi], acc[pi][hi]);
    }
    __syncthreads();                    // done reading sA — reuse as reduce buffer

    // Epilogue: relu(+b2), sum over this thread's 8 pairs
    const int hb = tx * 8;
    float part[8], b2v[8];
#pragma unroll
    for (int hi = 0; hi < 8; ++hi) { part[hi] = 0.f; b2v[hi] = b2[hb + hi]; }
#pragma unroll
    for (int pi = 0; pi < 8; ++pi)
#pragma unroll
        for (int hi = 0; hi < 8; ++hi) {
            const float u = acc[pi][hi] + b2v[hi];
            part[hi] += u > 0.f ? u : 0.f;
        }

    // Cross-thread reduce over ty (16 rows of partials per h)
    float* red = sA;                    // 16 x 128
#pragma unroll
    for (int hi = 0; hi < 8; ++hi) red[ty * 128 + hb + hi] = part[hi];
    __syncthreads();
    if (t < 128) {
        float s = 0.f;
#pragma unroll
        for (int r = 0; r < 16; ++r) s += red[r * 128 + t];
        atomicAdd(&g_pooled[b * H + t], s);
    }
}

// ---------------------------------------------------------------------------
// Kernel C: tail. pooled @ W3 + N^2*b3 -> relu(@V1 + c1) -> @V2 + c2.
// One block, 128 threads, both batches.
// ---------------------------------------------------------------------------
__global__ __launch_bounds__(128) void tail_kernel(const float* __restrict__ W3,
                                                   const float* __restrict__ b3,
                                                   const float* __restrict__ V1,
                                                   const float* __restrict__ c1,
                                                   const float* __restrict__ V2,
                                                   const float* __restrict__ c2,
                                                   float* __restrict__ out)
{
    __shared__ float sp[2][H];
    __shared__ float sq[2][H];
    const int t = threadIdx.x;

    sp[0][t] = g_pooled[t];
    sp[1][t] = g_pooled[H + t];
    __syncthreads();

    // pooled_rel = pooled @ W3 + N^2 * b3
#pragma unroll
    for (int b = 0; b < 2; ++b) {
        float s = 0.f;
        for (int k = 0; k < H; ++k) s = fmaf(sp[b][k], W3[k * H + t], s);
        sq[b][t] = s + 262144.0f * b3[t];       // N*N = 512*512
    }
    __syncthreads();

    // o = relu(pooled_rel @ V1 + c1)
    float ov[2];
#pragma unroll
    for (int b = 0; b < 2; ++b) {
        float s = c1[t];
        for (int k = 0; k < H; ++k) s = fmaf(sq[b][k], V1[k * H + t], s);
        ov[b] = s > 0.f ? s : 0.f;
    }
    __syncthreads();
    sp[0][t] = ov[0];
    sp[1][t] = ov[1];
    __syncthreads();

    // out = o @ V2 + c2
    if (t < OUTD) {
#pragma unroll
        for (int b = 0; b < 2; ++b) {
            float s = c2[t];
            for (int k = 0; k < H; ++k) s = fmaf(sp[b][k], V2[k * OUTD + t], s);
            out[b * OUTD + t] = s;
        }
    }
}

// ---------------------------------------------------------------------------
extern "C" void kernel_launch(void* const* d_in, const int* in_sizes, int n_in,
                              void* d_out, int out_size)
{
    const float* x  = (const float*)d_in[0];
    const float* W1 = (const float*)d_in[1];
    const float* b1 = (const float*)d_in[2];
    const float* W2 = (const float*)d_in[3];
    const float* b2 = (const float*)d_in[4];
    const float* W3 = (const float*)d_in[5];
    const float* b3 = (const float*)d_in[6];
    const float* V1 = (const float*)d_in[7];
    const float* c1 = (const float*)d_in[8];
    const float* V2 = (const float*)d_in[9];
    const float* c2 = (const float*)d_in[10];
    float* out = (float*)d_out;

    prep_kernel<<<(B_SZ * N_TOK) / 8, 128>>>(x, W1, b1);

    const size_t smem_bytes = (size_t)(16384 + 16384 + 8 * 132 + 16 * 132) * sizeof(float);
    cudaFuncSetAttribute(pair_kernel, cudaFuncAttributeMaxDynamicSharedMemorySize,
                         (int)smem_bytes);
    dim3 grid(N_TOK / TJ, N_TOK / TI, B_SZ);
    pair_kernel<<<grid, 256, smem_bytes>>>(W2, b2);

    tail_kernel<<<1, 128>>>(W3, b3, V1, c1, V2, c2, out);
}

// round 7
// speedup vs baseline: 4.9919x; 4.9919x over previous
#include <cuda_runtime.h>
#include <cuda_fp16.h>
#include <cstdint>

#define B_SZ  2
#define N_TOK 512
#define D     64
#define H     128
#define OUTD  64

// ---------------------------------------------------------------------------
// Scratch (device globals)
// ---------------------------------------------------------------------------
__device__ float    g_xa[B_SZ * N_TOK * H];        // x @ W1[:D] + b1  (fp32)
__device__ float    g_xb[B_SZ * N_TOK * H];        // x @ W1[D:]       (fp32)
__device__ uint32_t g_W2t[H * H / 2];              // W2^T fp16, [n][k] (half2 words)
__device__ float    g_pooled_part[B_SZ * 32 * H];  // 32 contention slots per batch

__device__ __forceinline__ uint32_t smem_u32(const void* p) {
    uint32_t a;
    asm("{ .reg .u64 tmp; cvta.to.shared.u64 tmp, %1; cvt.u32.u64 %0, tmp; }"
        : "=r"(a) : "l"(p));
    return a;
}
__device__ __forceinline__ void ldmatrix_x4(uint32_t* r, uint32_t addr) {
    asm volatile("ldmatrix.sync.aligned.m8n8.x4.shared.b16 {%0,%1,%2,%3}, [%4];"
        : "=r"(r[0]), "=r"(r[1]), "=r"(r[2]), "=r"(r[3]) : "r"(addr));
}
__device__ __forceinline__ void mma_f16(float* c, const uint32_t* a,
                                        uint32_t b0, uint32_t b1) {
    asm volatile(
        "mma.sync.aligned.m16n8k16.row.col.f32.f16.f16.f32 "
        "{%0,%1,%2,%3}, {%4,%5,%6,%7}, {%8,%9}, {%0,%1,%2,%3};"
        : "+f"(c[0]), "+f"(c[1]), "+f"(c[2]), "+f"(c[3])
        : "r"(a[0]), "r"(a[1]), "r"(a[2]), "r"(a[3]), "r"(b0), "r"(b1));
}

// SMEM layout (bytes). Row stride for A/B tiles: 272B (256B data + 16B pad)
// -> consecutive rows shift 4 banks: conflict-free ldmatrix + linear stores.
#define RSTRIDE  272u
#define OFF_A    0u
#define OFF_B    34816u     // 128*272
#define OFF_XA   69632u     // 8  rows x 128 f32
#define OFF_XB   73728u     // 16 rows x 128 f32
#define OFF_B2   81920u     // 128 f32
#define OFF_RED  82432u     // 8 x 32 f32
#define SMEM_BYTES 83456u

// ---------------------------------------------------------------------------
// prep: xa/xb = x @ W1 halves (b1 folded into xa), fp32 out. 256 x 128.
// ---------------------------------------------------------------------------
__global__ __launch_bounds__(128) void prep_kernel(const float* __restrict__ x,
                                                   const float* __restrict__ W1,
                                                   const float* __restrict__ b1)
{
    __shared__ float sx[4][D];
    const int t = threadIdx.x;
    const int row0 = blockIdx.x * 4;

    for (int e = t; e < 4 * D; e += 128) sx[e >> 6][e & 63] = x[row0 * D + e];
    __syncthreads();

    const int h = t;
    float accA[4] = {0.f, 0.f, 0.f, 0.f}, accB[4] = {0.f, 0.f, 0.f, 0.f};
#pragma unroll 8
    for (int d = 0; d < D; ++d) {
        const float wa = W1[d * H + h];
        const float wb = W1[(D + d) * H + h];
#pragma unroll
        for (int r = 0; r < 4; ++r) {
            accA[r] = fmaf(sx[r][d], wa, accA[r]);
            accB[r] = fmaf(sx[r][d], wb, accB[r]);
        }
    }
    const float bb = b1[h];
#pragma unroll
    for (int r = 0; r < 4; ++r) {
        g_xa[(row0 + r) * H + h] = accA[r] + bb;
        g_xb[(row0 + r) * H + h] = accB[r];
    }
}

// ---------------------------------------------------------------------------
// conv: W2 fp32 [k][h] -> W2^T fp16 [n][k] (half2 words). Zeros pooled slots.
// 128 blocks (n) x 64 threads (k-word).
// ---------------------------------------------------------------------------
__global__ void conv_w2_kernel(const float* __restrict__ W2)
{
    const int n = blockIdx.x;
    const int kk = threadIdx.x;
    __half2 v = __floats2half2_rn(W2[(2 * kk) * H + n], W2[(2 * kk + 1) * H + n]);
    g_W2t[n * 64 + kk] = *(uint32_t*)&v;
    g_pooled_part[blockIdx.x * 64 + threadIdx.x] = 0.f;   // 8192 == 2*32*128
}

// ---------------------------------------------------------------------------
// pair kernel: 128 pairs/CTA (16 i x 8 j), fp16 mma.sync GEMM vs W2^T,
// A = fp16( relu(fp32 xa[j] + fp32 xb[i]) )  -- single rounding.
// epilogue relu(+b2) + pair-sum -> slotted atomicAdd.
// ---------------------------------------------------------------------------
__global__ __launch_bounds__(256, 2) void pair_mma_kernel(const float* __restrict__ b2)
{
    extern __shared__ __align__(16) char smem[];
    const uint32_t S0 = smem_u32(smem);

    const int t = threadIdx.x;
    const int lane = t & 31, w = t >> 5;
    const int wm = w >> 2, wn = w & 3;          // 2 x 4 warp grid
    const int b  = blockIdx.z;
    const int j0 = blockIdx.x * 8;
    const int i0 = blockIdx.y * 16;

    // ---- stage W2^T (fp16) into padded smem rows ----
    {
        uint32_t* dstW = (uint32_t*)(smem + OFF_B);
        const uint32_t* srcW = g_W2t;
#pragma unroll
        for (int it = 0; it < 32; ++it) {
            const int e = t + 256 * it;         // [0, 8192)
            dstW[(e >> 6) * 68 + (e & 63)] = srcW[e];
        }
    }
    // ---- stage xa/xb rows (fp32) + b2 ----
    {
        const float4* xaG = (const float4*)(g_xa + (size_t)(b * N_TOK + j0) * H);
        const float4* xbG = (const float4*)(g_xb + (size_t)(b * N_TOK + i0) * H);
        float4* sxa = (float4*)(smem + OFF_XA);
        float4* sxb = (float4*)(smem + OFF_XB);
        sxa[t] = xaG[t];                                    // 8*32 = 256 float4
        sxb[t] = xbG[t];
        sxb[t + 256] = xbG[t + 256];                        // 16*32 = 512 float4
        if (t < 128) ((float*)(smem + OFF_B2))[t] = b2[t];
    }
    __syncthreads();

    // ---- build A tile: row p = il*8+jl, A[p][k] = fp16(relu(xa+xb)) ----
    {
        const float* sxa = (const float*)(smem + OFF_XA);
        const float* sxb = (const float*)(smem + OFF_XB);
        uint32_t* sA = (uint32_t*)(smem + OFF_A);
#pragma unroll
        for (int it = 0; it < 32; ++it) {
            const int e = t + 256 * it;         // [0, 8192) half2 words
            const int row = e >> 6, q = e & 63;
            const int jl = row & 7, il = row >> 3;
            const float2 va = *(const float2*)&sxa[jl * H + 2 * q];
            const float2 vb = *(const float2*)&sxb[il * H + 2 * q];
            const __half2 h2 = __floats2half2_rn(fmaxf(va.x + vb.x, 0.f),
                                                 fmaxf(va.y + vb.y, 0.f));
            sA[row * 68 + q] = *(const uint32_t*)&h2;
        }
    }
    __syncthreads();

    // ---- main loop: 8 k-steps of m16n8k16 ----
    float acc[4][4][4];
#pragma unroll
    for (int a = 0; a < 4; ++a)
#pragma unroll
        for (int c = 0; c < 4; ++c)
#pragma unroll
            for (int r = 0; r < 4; ++r) acc[a][c][r] = 0.f;

    const uint32_t aBase = S0 + OFF_A
        + (uint32_t)(wm * 64 + (lane & 15)) * RSTRIDE + (uint32_t)((lane >> 4) << 4);
    const uint32_t bBase = S0 + OFF_B
        + (uint32_t)(wn * 32 + ((lane & 7) | ((lane >> 4) << 3))) * RSTRIDE
        + (uint32_t)(((lane >> 3) & 1) << 4);

#pragma unroll
    for (int ks = 0; ks < 8; ++ks) {
        const uint32_t kb = (uint32_t)ks * 32u;
        uint32_t a_frag[4][4], b_frag[2][4];
#pragma unroll
        for (int mb = 0; mb < 4; ++mb)
            ldmatrix_x4(a_frag[mb], aBase + (uint32_t)mb * (16u * RSTRIDE) + kb);
#pragma unroll
        for (int nb = 0; nb < 2; ++nb)
            ldmatrix_x4(b_frag[nb], bBase + (uint32_t)nb * (16u * RSTRIDE) + kb);
#pragma unroll
        for (int mb = 0; mb < 4; ++mb)
#pragma unroll
            for (int nb = 0; nb < 2; ++nb) {
                mma_f16(acc[mb][nb * 2 + 0], a_frag[mb], b_frag[nb][0], b_frag[nb][1]);
                mma_f16(acc[mb][nb * 2 + 1], a_frag[mb], b_frag[nb][2], b_frag[nb][3]);
            }
    }

    // ---- epilogue: relu(+b2), sum over 128 pairs ----
    const float* sb2 = (const float*)(smem + OFF_B2);
    float* red = (float*)(smem + OFF_RED);
#pragma unroll
    for (int n8 = 0; n8 < 4; ++n8) {
        const int colA = wn * 32 + n8 * 8 + (lane & 3) * 2;
        const float b2a = sb2[colA], b2b = sb2[colA + 1];
        float pa = 0.f, pb = 0.f;
#pragma unroll
        for (int mb = 0; mb < 4; ++mb) {
            const float* c = acc[mb][n8];
            pa += fmaxf(c[0] + b2a, 0.f) + fmaxf(c[2] + b2a, 0.f);
            pb += fmaxf(c[1] + b2b, 0.f) + fmaxf(c[3] + b2b, 0.f);
        }
#pragma unroll
        for (int s = 16; s >= 4; s >>= 1) {
            pa += __shfl_xor_sync(0xFFFFFFFFu, pa, s);
            pb += __shfl_xor_sync(0xFFFFFFFFu, pb, s);
        }
        if (lane < 4) {
            red[w * 32 + n8 * 8 + lane * 2]     = pa;
            red[w * 32 + n8 * 8 + lane * 2 + 1] = pb;
        }
    }
    __syncthreads();
    if (t < 128) {
        const int cl = t & 31, wnb = t >> 5;
        const float s = red[wnb * 32 + cl] + red[(4 + wnb) * 32 + cl];
        const int slot = blockIdx.x & 31;
        atomicAdd(&g_pooled_part[(b * 32 + slot) * H + t], s);
    }
}

// ---------------------------------------------------------------------------
// tail: pooled @ W3 + N^2*b3 -> relu(@V1+c1) -> @V2+c2
// ---------------------------------------------------------------------------
__global__ __launch_bounds__(128) void tail_kernel(const float* __restrict__ W3,
                                                   const float* __restrict__ b3,
                                                   const float* __restrict__ V1,
                                                   const float* __restrict__ c1,
                                                   const float* __restrict__ V2,
                                                   const float* __restrict__ c2,
                                                   float* __restrict__ out)
{
    __shared__ float sp[2][H];
    __shared__ float sq[2][H];
    const int t = threadIdx.x;

#pragma unroll
    for (int b = 0; b < 2; ++b) {
        float s = 0.f;
#pragma unroll 8
        for (int sl = 0; sl < 32; ++sl) s += g_pooled_part[(b * 32 + sl) * H + t];
        sp[b][t] = s;
    }
    __syncthreads();

#pragma unroll
    for (int b = 0; b < 2; ++b) {
        float s0 = 0.f, s1 = 0.f, s2 = 0.f, s3 = 0.f;
#pragma unroll 4
        for (int k = 0; k < H; k += 4) {
            s0 = fmaf(sp[b][k],     W3[k * H + t],       s0);
            s1 = fmaf(sp[b][k + 1], W3[(k + 1) * H + t], s1);
            s2 = fmaf(sp[b][k + 2], W3[(k + 2) * H + t], s2);
            s3 = fmaf(sp[b][k + 3], W3[(k + 3) * H + t], s3);
        }
        sq[b][t] = (s0 + s1) + (s2 + s3) + 262144.0f * b3[t];  // N*N
    }
    __syncthreads();

    float ov[2];
#pragma unroll
    for (int b = 0; b < 2; ++b) {
        float s0 = c1[t], s1 = 0.f, s2 = 0.f, s3 = 0.f;
#pragma unroll 4
        for (int k = 0; k < H; k += 4) {
            s0 = fmaf(sq[b][k],     V1[k * H + t],       s0);
            s1 = fmaf(sq[b][k + 1], V1[(k + 1) * H + t], s1);
            s2 = fmaf(sq[b][k + 2], V1[(k + 2) * H + t], s2);
            s3 = fmaf(sq[b][k + 3], V1[(k + 3) * H + t], s3);
        }
        const float v = (s0 + s1) + (s2 + s3);
        ov[b] = v > 0.f ? v : 0.f;
    }
    __syncthreads();
    sp[0][t] = ov[0];
    sp[1][t] = ov[1];
    __syncthreads();

    if (t < OUTD) {
#pragma unroll
        for (int b = 0; b < 2; ++b) {
            float s = c2[t];
            for (int k = 0; k < H; ++k) s = fmaf(sp[b][k], V2[k * OUTD + t], s);
            out[b * OUTD + t] = s;
        }
    }
}

// ---------------------------------------------------------------------------
extern "C" void kernel_launch(void* const* d_in, const int* in_sizes, int n_in,
                              void* d_out, int out_size)
{
    const float* x  = (const float*)d_in[0];
    const float* W1 = (const float*)d_in[1];
    const float* b1 = (const float*)d_in[2];
    const float* W2 = (const float*)d_in[3];
    const float* b2 = (const float*)d_in[4];
    const float* W3 = (const float*)d_in[5];
    const float* b3 = (const float*)d_in[6];
    const float* V1 = (const float*)d_in[7];
    const float* c1 = (const float*)d_in[8];
    const float* V2 = (const float*)d_in[9];
    const float* c2 = (const float*)d_in[10];
    float* out = (float*)d_out;

    prep_kernel<<<(B_SZ * N_TOK) / 4, 128>>>(x, W1, b1);
    conv_w2_kernel<<<H, 64>>>(W2);

    cudaFuncSetAttribute(pair_mma_kernel, cudaFuncAttributeMaxDynamicSharedMemorySize,
                         (int)SMEM_BYTES);
    dim3 grid(N_TOK / 8, N_TOK / 16, B_SZ);
    pair_mma_kernel<<<grid, 256, SMEM_BYTES>>>(b2);

    tail_kernel<<<1, 128>>>(W3, b3, V1, c1, V2, c2, out);
}

// round 8
// speedup vs baseline: 5.8198x; 1.1658x over previous
#include <cuda_runtime.h>
#include <cuda_fp16.h>
#include <cstdint>

#define B_SZ  2
#define N_TOK 512
#define D     64
#define H     128
#define OUTD  64

// ---------------------------------------------------------------------------
// Scratch (device globals)
// ---------------------------------------------------------------------------
__device__ float    g_xa[B_SZ * N_TOK * H];        // x @ W1[:D] + b1  (fp32)
__device__ float    g_xb[B_SZ * N_TOK * H];        // x @ W1[D:]       (fp32)
__device__ uint32_t g_W2t[H * H / 2];              // W2^T fp16, [n][k] (half2 words)
__device__ float    g_pooled_part[B_SZ * 32 * H];  // 32 contention slots per batch

__device__ __forceinline__ uint32_t smem_u32(const void* p) {
    uint32_t a;
    asm("{ .reg .u64 tmp; cvta.to.shared.u64 tmp, %1; cvt.u32.u64 %0, tmp; }"
        : "=r"(a) : "l"(p));
    return a;
}
__device__ __forceinline__ void ldmatrix_x4(uint32_t* r, uint32_t addr) {
    asm volatile("ldmatrix.sync.aligned.m8n8.x4.shared.b16 {%0,%1,%2,%3}, [%4];"
        : "=r"(r[0]), "=r"(r[1]), "=r"(r[2]), "=r"(r[3]) : "r"(addr));
}
__device__ __forceinline__ void mma_f16(float* c, const uint32_t* a,
                                        uint32_t b0, uint32_t b1) {
    asm volatile(
        "mma.sync.aligned.m16n8k16.row.col.f32.f16.f16.f32 "
        "{%0,%1,%2,%3}, {%4,%5,%6,%7}, {%8,%9}, {%0,%1,%2,%3};"
        : "+f"(c[0]), "+f"(c[1]), "+f"(c[2]), "+f"(c[3])
        : "r"(a[0]), "r"(a[1]), "r"(a[2]), "r"(a[3]), "r"(b0), "r"(b1));
}

// SMEM layout (bytes). Row stride for A/B tiles: 272B (256B data + 16B pad)
#define RSTRIDE  272u
#define OFF_A    0u
#define OFF_B    34816u     // 128*272
#define OFF_XA   69632u     // 8  rows x 128 f32
#define OFF_XB   73728u     // 16 rows x 128 f32
#define OFF_B2   81920u     // 128 f32
#define OFF_RED  82432u     // 8 x 32 f32
#define SMEM_BYTES 83456u

// ---------------------------------------------------------------------------
// prep: xa/xb = x @ W1 halves (b1 folded into xa), fp32 out.
// 512 blocks x 128 threads, 2 rows/block (short serial chains, high MLP).
// ---------------------------------------------------------------------------
__global__ __launch_bounds__(128) void prep_kernel(const float* __restrict__ x,
                                                   const float* __restrict__ W1,
                                                   const float* __restrict__ b1)
{
    __shared__ float sx[2][D];
    const int t = threadIdx.x;
    const int row0 = blockIdx.x * 2;

    if (t < 2 * D) sx[t >> 6][t & 63] = x[row0 * D + t];
    __syncthreads();

    const int h = t;
    float a0 = 0.f, a1 = 0.f, b0 = 0.f, b1v = 0.f;
#pragma unroll 16
    for (int d = 0; d < D; ++d) {
        const float wa = W1[d * H + h];
        const float wb = W1[(D + d) * H + h];
        a0  = fmaf(sx[0][d], wa, a0);
        a1  = fmaf(sx[1][d], wa, a1);
        b0  = fmaf(sx[0][d], wb, b0);
        b1v = fmaf(sx[1][d], wb, b1v);
    }
    const float bb = b1[h];
    g_xa[(row0    ) * H + h] = a0 + bb;
    g_xa[(row0 + 1) * H + h] = a1 + bb;
    g_xb[(row0    ) * H + h] = b0;
    g_xb[(row0 + 1) * H + h] = b1v;
}

// ---------------------------------------------------------------------------
// conv: W2 fp32 [k][h] -> W2^T fp16 [n][k] (half2 words). Zeros pooled slots.
// ---------------------------------------------------------------------------
__global__ void conv_w2_kernel(const float* __restrict__ W2)
{
    const int n = blockIdx.x;
    const int kk = threadIdx.x;
    __half2 v = __floats2half2_rn(W2[(2 * kk) * H + n], W2[(2 * kk + 1) * H + n]);
    g_W2t[n * 64 + kk] = *(uint32_t*)&v;
    g_pooled_part[blockIdx.x * 64 + threadIdx.x] = 0.f;   // 8192 == 2*32*128
}

// ---------------------------------------------------------------------------
// pair kernel: 128 pairs/CTA (16 i x 8 j), fp16 mma.sync GEMM vs W2^T,
// A = fp16( relu(fp32 xa[j] + fp32 xb[i]) )  -- single rounding.
// ---------------------------------------------------------------------------
__global__ __launch_bounds__(256, 2) void pair_mma_kernel(const float* __restrict__ b2)
{
    extern __shared__ __align__(16) char smem[];
    const uint32_t S0 = smem_u32(smem);

    const int t = threadIdx.x;
    const int lane = t & 31, w = t >> 5;
    const int wm = w >> 2, wn = w & 3;          // 2 x 4 warp grid
    const int b  = blockIdx.z;
    const int j0 = blockIdx.x * 8;
    const int i0 = blockIdx.y * 16;

    // ---- stage W2^T (fp16) into padded smem rows ----
    {
        uint32_t* dstW = (uint32_t*)(smem + OFF_B);
        const uint32_t* srcW = g_W2t;
#pragma unroll
        for (int it = 0; it < 32; ++it) {
            const int e = t + 256 * it;         // [0, 8192)
            dstW[(e >> 6) * 68 + (e & 63)] = srcW[e];
        }
    }
    // ---- stage xa/xb rows (fp32) + b2 ----
    {
        const float4* xaG = (const float4*)(g_xa + (size_t)(b * N_TOK + j0) * H);
        const float4* xbG = (const float4*)(g_xb + (size_t)(b * N_TOK + i0) * H);
        float4* sxa = (float4*)(smem + OFF_XA);
        float4* sxb = (float4*)(smem + OFF_XB);
        sxa[t] = xaG[t];                                    // 8*32 = 256 float4
        sxb[t] = xbG[t];
        sxb[t + 256] = xbG[t + 256];                        // 16*32 = 512 float4
        if (t < 128) ((float*)(smem + OFF_B2))[t] = b2[t];
    }
    __syncthreads();

    // ---- build A tile: row p = il*8+jl, A[p][k] = fp16(relu(xa+xb)) ----
    {
        const float* sxa = (const float*)(smem + OFF_XA);
        const float* sxb = (const float*)(smem + OFF_XB);
        uint32_t* sA = (uint32_t*)(smem + OFF_A);
#pragma unroll
        for (int it = 0; it < 32; ++it) {
            const int e = t + 256 * it;         // [0, 8192) half2 words
            const int row = e >> 6, q = e & 63;
            const int jl = row & 7, il = row >> 3;
            const float2 va = *(const float2*)&sxa[jl * H + 2 * q];
            const float2 vb = *(const float2*)&sxb[il * H + 2 * q];
            const __half2 h2 = __floats2half2_rn(fmaxf(va.x + vb.x, 0.f),
                                                 fmaxf(va.y + vb.y, 0.f));
            sA[row * 68 + q] = *(const uint32_t*)&h2;
        }
    }
    __syncthreads();

    // ---- main loop: 8 k-steps of m16n8k16 ----
    float acc[4][4][4];
#pragma unroll
    for (int a = 0; a < 4; ++a)
#pragma unroll
        for (int c = 0; c < 4; ++c)
#pragma unroll
            for (int r = 0; r < 4; ++r) acc[a][c][r] = 0.f;

    const uint32_t aBase = S0 + OFF_A
        + (uint32_t)(wm * 64 + (lane & 15)) * RSTRIDE + (uint32_t)((lane >> 4) << 4);
    const uint32_t bBase = S0 + OFF_B
        + (uint32_t)(wn * 32 + ((lane & 7) | ((lane >> 4) << 3))) * RSTRIDE
        + (uint32_t)(((lane >> 3) & 1) << 4);

#pragma unroll
    for (int ks = 0; ks < 8; ++ks) {
        const uint32_t kb = (uint32_t)ks * 32u;
        uint32_t a_frag[4][4], b_frag[2][4];
#pragma unroll
        for (int mb = 0; mb < 4; ++mb)
            ldmatrix_x4(a_frag[mb], aBase + (uint32_t)mb * (16u * RSTRIDE) + kb);
#pragma unroll
        for (int nb = 0; nb < 2; ++nb)
            ldmatrix_x4(b_frag[nb], bBase + (uint32_t)nb * (16u * RSTRIDE) + kb);
#pragma unroll
        for (int mb = 0; mb < 4; ++mb)
#pragma unroll
            for (int nb = 0; nb < 2; ++nb) {
                mma_f16(acc[mb][nb * 2 + 0], a_frag[mb], b_frag[nb][0], b_frag[nb][1]);
                mma_f16(acc[mb][nb * 2 + 1], a_frag[mb], b_frag[nb][2], b_frag[nb][3]);
            }
    }

    // ---- epilogue: relu(+b2), sum over 128 pairs ----
    const float* sb2 = (const float*)(smem + OFF_B2);
    float* red = (float*)(smem + OFF_RED);
#pragma unroll
    for (int n8 = 0; n8 < 4; ++n8) {
        const int colA = wn * 32 + n8 * 8 + (lane & 3) * 2;
        const float b2a = sb2[colA], b2b = sb2[colA + 1];
        float pa = 0.f, pb = 0.f;
#pragma unroll
        for (int mb = 0; mb < 4; ++mb) {
            const float* c = acc[mb][n8];
            pa += fmaxf(c[0] + b2a, 0.f) + fmaxf(c[2] + b2a, 0.f);
            pb += fmaxf(c[1] + b2b, 0.f) + fmaxf(c[3] + b2b, 0.f);
        }
#pragma unroll
        for (int s = 16; s >= 4; s >>= 1) {
            pa += __shfl_xor_sync(0xFFFFFFFFu, pa, s);
            pb += __shfl_xor_sync(0xFFFFFFFFu, pb, s);
        }
        if (lane < 4) {
            red[w * 32 + n8 * 8 + lane * 2]     = pa;
            red[w * 32 + n8 * 8 + lane * 2 + 1] = pb;
        }
    }
    __syncthreads();
    if (t < 128) {
        const int cl = t & 31, wnb = t >> 5;
        const float s = red[wnb * 32 + cl] + red[(4 + wnb) * 32 + cl];
        const int slot = blockIdx.x & 31;
        atomicAdd(&g_pooled_part[(b * 32 + slot) * H + t], s);
    }
}

// ---------------------------------------------------------------------------
// tail v2: grid=2 (one CTA per batch), 512 threads, k-split-4 per layer with
// smem reduce. Kills the 41.6us serial-latency tail.
// ---------------------------------------------------------------------------
__global__ __launch_bounds__(512) void tail_kernel(const float* __restrict__ W3,
                                                   const float* __restrict__ b3,
                                                   const float* __restrict__ V1,
                                                   const float* __restrict__ c1,
                                                   const float* __restrict__ V2,
                                                   const float* __restrict__ c2,
                                                   float* __restrict__ out)
{
    __shared__ float sp[H];        // pooled, then reused as o
    __shared__ float sq[H];        // pooled_rel
    __shared__ float part[4][H];
    const int b = blockIdx.x;
    const int t = threadIdx.x;
    const int ks = t >> 7, h = t & 127;     // k-slice, output index
    const int k0 = ks * 32;

    // stage pooled: sum the 32 contention slots (threads 0..127)
    if (t < H) {
        float s = 0.f;
#pragma unroll 8
        for (int sl = 0; sl < 32; ++sl) s += g_pooled_part[(b * 32 + sl) * H + t];
        sp[t] = s;
    }
    __syncthreads();

    // layer 1: sq = pooled @ W3 + N^2*b3
    {
        float s0 = 0.f, s1 = 0.f, s2 = 0.f, s3 = 0.f;
#pragma unroll 8
        for (int k = 0; k < 32; k += 4) {
            s0 = fmaf(sp[k0 + k],     W3[(k0 + k) * H + h],     s0);
            s1 = fmaf(sp[k0 + k + 1], W3[(k0 + k + 1) * H + h], s1);
            s2 = fmaf(sp[k0 + k + 2], W3[(k0 + k + 2) * H + h], s2);
            s3 = fmaf(sp[k0 + k + 3], W3[(k0 + k + 3) * H + h], s3);
        }
        part[ks][h] = (s0 + s1) + (s2 + s3);
    }
    __syncthreads();
    if (t < H)
        sq[t] = part[0][t] + part[1][t] + part[2][t] + part[3][t] + 262144.0f * b3[t];
    __syncthreads();

    // layer 2: o = relu(sq @ V1 + c1)
    {
        float s0 = 0.f, s1 = 0.f, s2 = 0.f, s3 = 0.f;
#pragma unroll 8
        for (int k = 0; k < 32; k += 4) {
            s0 = fmaf(sq[k0 + k],     V1[(k0 + k) * H + h],     s0);
            s1 = fmaf(sq[k0 + k + 1], V1[(k0 + k + 1) * H + h], s1);
            s2 = fmaf(sq[k0 + k + 2], V1[(k0 + k + 2) * H + h], s2);
            s3 = fmaf(sq[k0 + k + 3], V1[(k0 + k + 3) * H + h], s3);
        }
        part[ks][h] = (s0 + s1) + (s2 + s3);
    }
    __syncthreads();
    if (t < H) {
        const float v = part[0][t] + part[1][t] + part[2][t] + part[3][t] + c1[t];
        sp[t] = v > 0.f ? v : 0.f;          // sp reused as o
    }
    __syncthreads();

    // layer 3: out = o @ V2 + c2   (256 threads: 4 k-slices x 64 outputs)
    if (t < 256) {
        const int ks3 = t >> 6, o = t & 63;
        const int kb = ks3 * 32;
        float s0 = 0.f, s1 = 0.f, s2 = 0.f, s3 = 0.f;
#pragma unroll 8
        for (int k = 0; k < 32; k += 4) {
            s0 = fmaf(sp[kb + k],     V2[(kb + k) * OUTD + o],     s0);
            s1 = fmaf(sp[kb + k + 1], V2[(kb + k + 1) * OUTD + o], s1);
            s2 = fmaf(sp[kb + k + 2], V2[(kb + k + 2) * OUTD + o], s2);
            s3 = fmaf(sp[kb + k + 3], V2[(kb + k + 3) * OUTD + o], s3);
        }
        part[ks3][o] = (s0 + s1) + (s2 + s3);
    }
    __syncthreads();
    if (t < OUTD)
        out[b * OUTD + t] = part[0][t] + part[1][t] + part[2][t] + part[3][t] + c2[t];
}

// ---------------------------------------------------------------------------
extern "C" void kernel_launch(void* const* d_in, const int* in_sizes, int n_in,
                              void* d_out, int out_size)
{
    const float* x  = (const float*)d_in[0];
    const float* W1 = (const float*)d_in[1];
    const float* b1 = (const float*)d_in[2];
    const float* W2 = (const float*)d_in[3];
    const float* b2 = (const float*)d_in[4];
    const float* W3 = (const float*)d_in[5];
    const float* b3 = (const float*)d_in[6];
    const float* V1 = (const float*)d_in[7];
    const float* c1 = (const float*)d_in[8];
    const float* V2 = (const float*)d_in[9];
    const float* c2 = (const float*)d_in[10];
    float* out = (float*)d_out;

    prep_kernel<<<(B_SZ * N_TOK) / 2, 128>>>(x, W1, b1);
    conv_w2_kernel<<<H, 64>>>(W2);

    cudaFuncSetAttribute(pair_mma_kernel, cudaFuncAttributeMaxDynamicSharedMemorySize,
                         (int)SMEM_BYTES);
    dim3 grid(N_TOK / 8, N_TOK / 16, B_SZ);
    pair_mma_kernel<<<grid, 256, SMEM_BYTES>>>(b2);

    tail_kernel<<<B_SZ, 512>>>(W3, b3, V1, c1, V2, c2, out);
}

// round 9
// speedup vs baseline: 6.8285x; 1.1733x over previous
#include <cuda_runtime.h>
#include <cuda_fp16.h>
#include <cstdint>

#define B_SZ  2
#define N_TOK 512
#define D     64
#define H     128
#define OUTD  64
#define NTILES 4096
#define PAIR_GRID 296

// ---------------------------------------------------------------------------
// Scratch (device globals)
// ---------------------------------------------------------------------------
__device__ float    g_xa[B_SZ * N_TOK * H];        // x @ W1[:D] + b1  (fp32)
__device__ float    g_xb[B_SZ * N_TOK * H];        // x @ W1[D:]       (fp32)
__device__ uint32_t g_W2t[H * H / 2];              // W2^T fp16, [n][k] (half2 words)
__device__ float    g_pooled_part[B_SZ * 32 * H];  // 32 contention slots per batch
__device__ float    g_M[H * H];                    // W3 @ V1 (fp32)
__device__ float    g_d[H];                        // N^2*(b3@V1) + c1
__device__ int      g_ticket;                      // pair-kernel work queue
__device__ float    g_dummy;                       // keep warm-loads alive

__device__ __forceinline__ uint32_t smem_u32(const void* p) {
    uint32_t a;
    asm("{ .reg .u64 tmp; cvta.to.shared.u64 tmp, %1; cvt.u32.u64 %0, tmp; }"
        : "=r"(a) : "l"(p));
    return a;
}
__device__ __forceinline__ void ldmatrix_x4(uint32_t* r, uint32_t addr) {
    asm volatile("ldmatrix.sync.aligned.m8n8.x4.shared.b16 {%0,%1,%2,%3}, [%4];"
        : "=r"(r[0]), "=r"(r[1]), "=r"(r[2]), "=r"(r[3]) : "r"(addr));
}
__device__ __forceinline__ void mma_f16(float* c, const uint32_t* a,
                                        uint32_t b0, uint32_t b1) {
    asm volatile(
        "mma.sync.aligned.m16n8k16.row.col.f32.f16.f16.f32 "
        "{%0,%1,%2,%3}, {%4,%5,%6,%7}, {%8,%9}, {%0,%1,%2,%3};"
        : "+f"(c[0]), "+f"(c[1]), "+f"(c[2]), "+f"(c[3])
        : "r"(a[0]), "r"(a[1]), "r"(a[2]), "r"(a[3]), "r"(b0), "r"(b1));
}

// SMEM layout (bytes). Row stride for A/B tiles: 272B (256B data + 16B pad)
#define RSTRIDE  272u
#define OFF_A    0u
#define OFF_B    34816u     // 128*272
#define OFF_XA   69632u     // 8  rows x 128 f32
#define OFF_XB   73728u     // 16 rows x 128 f32
#define OFF_B2   81920u     // 128 f32
#define OFF_RED  82432u     // 8 x 32 f32
#define SMEM_BYTES 83456u

// ---------------------------------------------------------------------------
// Merged setup kernel. Block roles (long-pole MCOMP first):
//   [0,128)   MCOMP: g_M[k][h] = sum_m W3[k][m] * V1[m][h]
//   128       DVEC : g_d[h] = N^2*(b3@V1)[h] + c1[h]; reset ticket
//   [129,257) CONV : W2 -> W2^T fp16; zero pooled slots
//   [257,265) WARM : touch V2 into L2
//   [265,777) PREP : xa/xb = x @ W1 halves (b1 folded into xa)
// ---------------------------------------------------------------------------
__global__ __launch_bounds__(128) void setup_kernel(const float* __restrict__ x,
                                                    const float* __restrict__ W1,
                                                    const float* __restrict__ b1,
                                                    const float* __restrict__ W2,
                                                    const float* __restrict__ W3,
                                                    const float* __restrict__ b3,
                                                    const float* __restrict__ V1,
                                                    const float* __restrict__ c1,
                                                    const float* __restrict__ V2)
{
    __shared__ float sbuf[128];
    const int blk = blockIdx.x;
    const int t = threadIdx.x;

    if (blk < 128) {                       // ---- MCOMP ----
        const int k = blk;
        sbuf[t] = W3[k * H + t];
        __syncthreads();
        float a0 = 0.f, a1 = 0.f, a2 = 0.f, a3 = 0.f;
        float a4 = 0.f, a5 = 0.f, a6 = 0.f, a7 = 0.f;
#pragma unroll 4
        for (int m = 0; m < H; m += 8) {
            a0 = fmaf(sbuf[m    ], V1[(m    ) * H + t], a0);
            a1 = fmaf(sbuf[m + 1], V1[(m + 1) * H + t], a1);
            a2 = fmaf(sbuf[m + 2], V1[(m + 2) * H + t], a2);
            a3 = fmaf(sbuf[m + 3], V1[(m + 3) * H + t], a3);
            a4 = fmaf(sbuf[m + 4], V1[(m + 4) * H + t], a4);
            a5 = fmaf(sbuf[m + 5], V1[(m + 5) * H + t], a5);
            a6 = fmaf(sbuf[m + 6], V1[(m + 6) * H + t], a6);
            a7 = fmaf(sbuf[m + 7], V1[(m + 7) * H + t], a7);
        }
        g_M[k * H + t] = ((a0 + a1) + (a2 + a3)) + ((a4 + a5) + (a6 + a7));
    } else if (blk == 128) {               // ---- DVEC ----
        sbuf[t] = b3[t];
        __syncthreads();
        float a0 = 0.f, a1 = 0.f, a2 = 0.f, a3 = 0.f;
#pragma unroll 8
        for (int m = 0; m < H; m += 4) {
            a0 = fmaf(sbuf[m    ], V1[(m    ) * H + t], a0);
            a1 = fmaf(sbuf[m + 1], V1[(m + 1) * H + t], a1);
            a2 = fmaf(sbuf[m + 2], V1[(m + 2) * H + t], a2);
            a3 = fmaf(sbuf[m + 3], V1[(m + 3) * H + t], a3);
        }
        g_d[t] = 262144.0f * ((a0 + a1) + (a2 + a3)) + c1[t];
        if (t == 0) g_ticket = 0;
    } else if (blk < 257) {                // ---- CONV ----
        const int n = blk - 129;
        if (t < 64) {
            const int kk = t;
            __half2 v = __floats2half2_rn(W2[(2 * kk) * H + n],
                                          W2[(2 * kk + 1) * H + n]);
            g_W2t[n * 64 + kk] = *(uint32_t*)&v;
        } else {
            g_pooled_part[n * 64 + (t - 64)] = 0.f;   // 128*64 = 8192 slots
        }
    } else if (blk < 265) {                // ---- WARM V2 ----
        const int e = (blk - 257) * 1024 + t * 8;
        float s = 0.f;
#pragma unroll
        for (int i = 0; i < 8; ++i) s += V2[e + i];
        if (s == 1.2345e30f) g_dummy = s;
    } else {                               // ---- PREP ----
        const int row0 = (blk - 265) * 2;
        if (t < 2 * D) sbuf[t] = x[row0 * D + t];
        __syncthreads();
        const int h = t;
        float a0 = 0.f, a1 = 0.f, b0 = 0.f, b1v = 0.f;
#pragma unroll 16
        for (int d = 0; d < D; ++d) {
            const float wa = W1[d * H + h];
            const float wb = W1[(D + d) * H + h];
            a0  = fmaf(sbuf[d],      wa, a0);
            a1  = fmaf(sbuf[64 + d], wa, a1);
            b0  = fmaf(sbuf[d],      wb, b0);
            b1v = fmaf(sbuf[64 + d], wb, b1v);
        }
        const float bb = b1[h];
        g_xa[(row0    ) * H + h] = a0 + bb;
        g_xa[(row0 + 1) * H + h] = a1 + bb;
        g_xb[(row0    ) * H + h] = b0;
        g_xb[(row0 + 1) * H + h] = b1v;
    }
}

// ---------------------------------------------------------------------------
// Persistent pair kernel: 296 CTAs, ticket queue over 4096 tiles.
// W2 staged ONCE per CTA; per tile: stage xa/xb, build A=fp16(relu(xa+xb)),
// 8x m16n8k16 k-steps, epilogue relu(+b2)+pair-sum -> slotted atomicAdd.
// ---------------------------------------------------------------------------
__global__ __launch_bounds__(256, 2) void pair_mma_kernel(const float* __restrict__ b2)
{
    extern __shared__ __align__(16) char smem[];
    const uint32_t S0 = smem_u32(smem);
    __shared__ int s_tile;

    const int t = threadIdx.x;
    const int lane = t & 31, w = t >> 5;
    const int wm = w >> 2, wn = w & 3;          // 2 x 4 warp grid

    // ---- stage W2^T (fp16) into padded smem rows -- once per CTA ----
    {
        uint32_t* dstW = (uint32_t*)(smem + OFF_B);
        const uint32_t* srcW = g_W2t;
#pragma unroll
        for (int it = 0; it < 32; ++it) {
            const int e = t + 256 * it;         // [0, 8192)
            dstW[(e >> 6) * 68 + (e & 63)] = srcW[e];
        }
        if (t < 128) ((float*)(smem + OFF_B2))[t] = b2[t];
    }

    const uint32_t aBase = S0 + OFF_A
        + (uint32_t)(wm * 64 + (lane & 15)) * RSTRIDE + (uint32_t)((lane >> 4) << 4);
    const uint32_t bBase = S0 + OFF_B
        + (uint32_t)(wn * 32 + ((lane & 7) | ((lane >> 4) << 3))) * RSTRIDE
        + (uint32_t)(((lane >> 3) & 1) << 4);

    while (true) {
        if (t == 0) s_tile = atomicAdd(&g_ticket, 1);
        __syncthreads();
        const int tile = s_tile;
        if (tile >= NTILES) break;

        const int b  = tile >> 11;
        const int r  = tile & 2047;
        const int i0 = (r >> 6) * 16;
        const int jx = r & 63;
        const int j0 = jx * 8;

        // ---- stage xa/xb rows (fp32) ----
        {
            const float4* xaG = (const float4*)(g_xa + (size_t)(b * N_TOK + j0) * H);
            const float4* xbG = (const float4*)(g_xb + (size_t)(b * N_TOK + i0) * H);
            float4* sxa = (float4*)(smem + OFF_XA);
            float4* sxb = (float4*)(smem + OFF_XB);
            sxa[t] = xaG[t];                                // 8*32 = 256 float4
            sxb[t] = xbG[t];
            sxb[t + 256] = xbG[t + 256];                    // 16*32 = 512 float4
        }
        __syncthreads();

        // ---- build A tile: row p = il*8+jl, A[p][k] = fp16(relu(xa+xb)) ----
        {
            const float* sxa = (const float*)(smem + OFF_XA);
            const float* sxb = (const float*)(smem + OFF_XB);
            uint32_t* sA = (uint32_t*)(smem + OFF_A);
#pragma unroll
            for (int it = 0; it < 32; ++it) {
                const int e = t + 256 * it;     // [0, 8192) half2 words
                const int row = e >> 6, q = e & 63;
                const int jl = row & 7, il = row >> 3;
                const float2 va = *(const float2*)&sxa[jl * H + 2 * q];
                const float2 vb = *(const float2*)&sxb[il * H + 2 * q];
                const __half2 h2 = __floats2half2_rn(fmaxf(va.x + vb.x, 0.f),
                                                     fmaxf(va.y + vb.y, 0.f));
                sA[row * 68 + q] = *(const uint32_t*)&h2;
            }
        }
        __syncthreads();

        // ---- main loop: 8 k-steps of m16n8k16 ----
        float acc[4][4][4];
#pragma unroll
        for (int a = 0; a < 4; ++a)
#pragma unroll
            for (int c = 0; c < 4; ++c)
#pragma unroll
                for (int rr = 0; rr < 4; ++rr) acc[a][c][rr] = 0.f;

#pragma unroll
        for (int ks = 0; ks < 8; ++ks) {
            const uint32_t kb = (uint32_t)ks * 32u;
            uint32_t a_frag[4][4], b_frag[2][4];
#pragma unroll
            for (int mb = 0; mb < 4; ++mb)
                ldmatrix_x4(a_frag[mb], aBase + (uint32_t)mb * (16u * RSTRIDE) + kb);
#pragma unroll
            for (int nb = 0; nb < 2; ++nb)
                ldmatrix_x4(b_frag[nb], bBase + (uint32_t)nb * (16u * RSTRIDE) + kb);
#pragma unroll
            for (int mb = 0; mb < 4; ++mb)
#pragma unroll
                for (int nb = 0; nb < 2; ++nb) {
                    mma_f16(acc[mb][nb * 2 + 0], a_frag[mb], b_frag[nb][0], b_frag[nb][1]);
                    mma_f16(acc[mb][nb * 2 + 1], a_frag[mb], b_frag[nb][2], b_frag[nb][3]);
                }
        }

        // ---- epilogue: relu(+b2), sum over 128 pairs ----
        const float* sb2 = (const float*)(smem + OFF_B2);
        float* red = (float*)(smem + OFF_RED);
#pragma unroll
        for (int n8 = 0; n8 < 4; ++n8) {
            const int colA = wn * 32 + n8 * 8 + (lane & 3) * 2;
            const float b2a = sb2[colA], b2b = sb2[colA + 1];
            float pa = 0.f, pb = 0.f;
#pragma unroll
            for (int mb = 0; mb < 4; ++mb) {
                const float* c = acc[mb][n8];
                pa += fmaxf(c[0] + b2a, 0.f) + fmaxf(c[2] + b2a, 0.f);
                pb += fmaxf(c[1] + b2b, 0.f) + fmaxf(c[3] + b2b, 0.f);
            }
#pragma unroll
            for (int s = 16; s >= 4; s >>= 1) {
                pa += __shfl_xor_sync(0xFFFFFFFFu, pa, s);
                pb += __shfl_xor_sync(0xFFFFFFFFu, pb, s);
            }
            if (lane < 4) {
                red[w * 32 + n8 * 8 + lane * 2]     = pa;
                red[w * 32 + n8 * 8 + lane * 2 + 1] = pb;
            }
        }
        __syncthreads();
        if (t < 128) {
            const int cl = t & 31, wnb = t >> 5;
            const float s = red[wnb * 32 + cl] + red[(4 + wnb) * 32 + cl];
            atomicAdd(&g_pooled_part[(b * 32 + (jx & 31)) * H + t], s);
        }
    }
}

// ---------------------------------------------------------------------------
// tail v3: 2 layers. o = relu(pooled @ M + d); out = o @ V2 + c2.
// grid=2 (one CTA per batch), 1024 threads, k-split 8 per layer.
// ---------------------------------------------------------------------------
__global__ __launch_bounds__(1024) void tail_kernel(const float* __restrict__ V2,
                                                    const float* __restrict__ c2,
                                                    float* __restrict__ out)
{
    __shared__ float sp[H];          // pooled
    __shared__ float so[H];          // o
    __shared__ float part[8][H];
    const int b = blockIdx.x;
    const int t = threadIdx.x;

    // stage pooled: sum the 32 contention slots
    if (t < H) {
        float s = 0.f;
#pragma unroll 8
        for (int sl = 0; sl < 32; ++sl) s += g_pooled_part[(b * 32 + sl) * H + t];
        sp[t] = s;
    }
    __syncthreads();

    // layer 1: o = relu(pooled @ M + d)     (8 k-slices x 128 outputs)
    {
        const int ks = t >> 7, h = t & 127;
        const int k0 = ks * 16;
        float s0 = 0.f, s1 = 0.f, s2 = 0.f, s3 = 0.f;
#pragma unroll
        for (int k = 0; k < 16; k += 4) {
            s0 = fmaf(sp[k0 + k],     g_M[(k0 + k) * H + h],     s0);
            s1 = fmaf(sp[k0 + k + 1], g_M[(k0 + k + 1) * H + h], s1);
            s2 = fmaf(sp[k0 + k + 2], g_M[(k0 + k + 2) * H + h], s2);
            s3 = fmaf(sp[k0 + k + 3], g_M[(k0 + k + 3) * H + h], s3);
        }
        part[ks][h] = (s0 + s1) + (s2 + s3);
    }
    __syncthreads();
    if (t < H) {
        float v = g_d[t];
#pragma unroll
        for (int ks = 0; ks < 8; ++ks) v += part[ks][t];
        so[t] = v > 0.f ? v : 0.f;
    }
    __syncthreads();

    // layer 2: out = o @ V2 + c2            (8 k-slices x 64 outputs)
    if (t < 512) {
        const int ks = t >> 6, o = t & 63;
        const int k0 = ks * 16;
        float s0 = 0.f, s1 = 0.f, s2 = 0.f, s3 = 0.f;
#pragma unroll
        for (int k = 0; k < 16; k += 4) {
            s0 = fmaf(so[k0 + k],     V2[(k0 + k) * OUTD + o],     s0);
            s1 = fmaf(so[k0 + k + 1], V2[(k0 + k + 1) * OUTD + o], s1);
            s2 = fmaf(so[k0 + k + 2], V2[(k0 + k + 2) * OUTD + o], s2);
            s3 = fmaf(so[k0 + k + 3], V2[(k0 + k + 3) * OUTD + o], s3);
        }
        part[ks][o] = (s0 + s1) + (s2 + s3);
    }
    __syncthreads();
    if (t < OUTD) {
        float v = c2[t];
#pragma unroll
        for (int ks = 0; ks < 8; ++ks) v += part[ks][t];
        out[b * OUTD + t] = v;
    }
}

// ---------------------------------------------------------------------------
extern "C" void kernel_launch(void* const* d_in, const int* in_sizes, int n_in,
                              void* d_out, int out_size)
{
    const float* x  = (const float*)d_in[0];
    const float* W1 = (const float*)d_in[1];
    const float* b1 = (const float*)d_in[2];
    const float* W2 = (const float*)d_in[3];
    const float* b2 = (const float*)d_in[4];
    const float* W3 = (const float*)d_in[5];
    const float* b3 = (const float*)d_in[6];
    const float* V1 = (const float*)d_in[7];
    const float* c1 = (const float*)d_in[8];
    const float* V2 = (const float*)d_in[9];
    const float* c2 = (const float*)d_in[10];
    float* out = (float*)d_out;

    setup_kernel<<<777, 128>>>(x, W1, b1, W2, W3, b3, V1, c1, V2);

    cudaFuncSetAttribute(pair_mma_kernel, cudaFuncAttributeMaxDynamicSharedMemorySize,
                         (int)SMEM_BYTES);
    pair_mma_kernel<<<PAIR_GRID, 256, SMEM_BYTES>>>(b2);

    tail_kernel<<<B_SZ, 1024>>>(V2, c2, out);
}